// round 11
// baseline (speedup 1.0000x reference)
#include <cuda_runtime.h>
#include <cstdint>

typedef unsigned long long ull;

// ---------------- problem constants ----------------
#define NPART 32
#define L0 (2048*1024)
#define L1 2048
#define L2 (256*2048)
#define L3 256
#define SEG_B0 (L0)              // 2097152
#define SEG_B1 (SEG_B0 + L1)     // 2099200
#define SEG_B2 (SEG_B1 + L2)     // 2623488
#define P_TOT  (SEG_B2 + L3)     // 2623744
#define EPSV 0.1f

// ---- shared chunking: 256 k, divides every segment boundary; no tail ----
#define CH 256
#define NCH (P_TOT/CH)           // 10249 exact
#define ROW_B 1024

// ---- gram: 2 CTAs/SM ----
#define GSTAGES 3
#define GSTAGE_B (32*ROW_B)      // 32768
#define GOFF 1024
#define GSMEM (GOFF + GSTAGES*GSTAGE_B)   // 99328 -> 2 CTAs/SM
#define NBLK1 296
#define NWARP1 10
#define GPW 9                    // producer warp (highest priority)

// ---- apply: 2 CTAs/SM (R8 config, unchanged) ----
#define ASTAGES 3
#define ASTAGE_B (32*ROW_B)      // 32768
#define AOFF 9216                // mbar(64) + coef table(8KB)
#define ASMEM (AOFF + ASTAGES*ASTAGE_B)   // 107520 -> 2 CTAs/SM
#define NBLK2 296
#define APW 7                    // producer warp

// ---------------- scratch ----------------
__device__ float  g_Gpart[NBLK1 * NWARP1 * 64];
__device__ float2 g_Cd[1024];        // g_Cd[j*32+i] = (C[i][j], C[i][j])

// upper-triangular 4x4 tile grid of 8x8 tiles
__constant__ int c_TBI[NWARP1] = {0,0,0,0,1,1,1,2,2,3};
__constant__ int c_TBJ[NWARP1] = {0,1,2,3,1,2,3,2,3,3};

// ---------------- PTX helpers ----------------
__device__ __forceinline__ void ffma2(ull &d, ull a, ull b) {
    asm("fma.rn.f32x2 %0, %1, %2, %0;" : "+l"(d) : "l"(a), "l"(b));
}
__device__ __forceinline__ void mbar_init(uint32_t mbar, uint32_t cnt) {
    asm volatile("mbarrier.init.shared.b64 [%0], %1;" :: "r"(mbar), "r"(cnt) : "memory");
}
__device__ __forceinline__ void mbar_expect_tx(uint32_t mbar, uint32_t bytes) {
    asm volatile("mbarrier.arrive.expect_tx.shared.b64 _, [%0], %1;"
                 :: "r"(mbar), "r"(bytes) : "memory");
}
__device__ __forceinline__ void mbar_wait(uint32_t mbar, uint32_t phase) {
    asm volatile(
        "{\n\t.reg .pred P;\n\t"
        "WL_%=:\n\t"
        "mbarrier.try_wait.parity.acquire.cta.shared::cta.b64 P, [%0], %1, 0x989680;\n\t"
        "@!P bra WL_%=;\n\t}"
        :: "r"(mbar), "r"(phase) : "memory");
}
__device__ __forceinline__ void bulk_g2s(uint32_t dst, const void* src,
                                         uint32_t bytes, uint32_t mbar) {
    asm volatile(
        "cp.async.bulk.shared::cluster.global.mbarrier::complete_tx::bytes [%0], [%1], %2, [%3];"
        :: "r"(dst), "l"(src), "r"(bytes), "r"(mbar) : "memory");
}

__device__ __forceinline__ const float* seg_base(int k,
        const float* __restrict__ W1, const float* __restrict__ b1,
        const float* __restrict__ W2, const float* __restrict__ b2,
        int &stride, int &kl) {
    if (k < SEG_B0) { stride = L0; kl = k;          return W1; }
    if (k < SEG_B1) { stride = L1; kl = k - SEG_B0; return b1; }
    if (k < SEG_B2) { stride = L2; kl = k - SEG_B1; return W2; }
    stride = L3; kl = k - SEG_B2; return b2;
}

// ---------------- pass 1: Gram (8x8 tiles, 10 warps, 2 CTAs/SM) ----------------
__global__ __launch_bounds__(320, 2)
void gram_kernel(const float* __restrict__ W1, const float* __restrict__ b1,
                 const float* __restrict__ W2, const float* __restrict__ b2) {
    extern __shared__ char sm[];
    const uint32_t sb = (uint32_t)__cvta_generic_to_shared(sm);
    const uint32_t mb_full = sb;
    const int tid  = threadIdx.x;
    const int w    = tid >> 5;
    const int lane = tid & 31;
    const int bi = c_TBI[w], bj = c_TBJ[w];

    const int per = NCH / NBLK1, rem = NCH % NBLK1;
    const int b   = blockIdx.x;
    const int c0  = b * per + (b < rem ? b : rem);
    const int cnt = per + (b < rem ? 1 : 0);

    if (tid == 0) {
#pragma unroll
        for (int s = 0; s < GSTAGES; s++) mbar_init(mb_full + s * 8, 1);
    }
    __syncthreads();

    auto load_chunk = [&](int n) {                // producer warp, lane-parallel
        const int buf = n % GSTAGES;
        int stride, kl;
        const float* base = seg_base((c0 + n) * CH, W1, b1, W2, b2, stride, kl);
        const uint32_t full = mb_full + buf * 8;
        if (lane == 0) mbar_expect_tx(full, 32 * 1024u);
        __syncwarp();
        bulk_g2s(sb + GOFF + buf * GSTAGE_B + lane * ROW_B,
                 base + (size_t)lane * stride + kl, 1024u, full);
    };

    if (w == GPW) {
        for (int n = 0; n < GSTAGES - 1 && n < cnt; n++) load_chunk(n);
    }

    ull acc[64];
#pragma unroll
    for (int p = 0; p < 64; p++) acc[p] = 0ull;

    int stg = 0, ph = 0;
    for (int it = 0; it < cnt; it++) {
        __syncthreads();
        if (w == GPW) {
            int n = it + GSTAGES - 1;
            if (n < cnt) load_chunk(n);
        }
        mbar_wait(mb_full + stg * 8, ph);

        const char* tb = sm + GOFF + stg * GSTAGE_B;
#pragma unroll
        for (int g = 0; g < 2; g++) {             // 2 groups of 128 k
            const char* tg = tb + g * 512 + lane * 16;
            ulonglong2 av[8];
#pragma unroll
            for (int r = 0; r < 8; r++)
                av[r] = *reinterpret_cast<const ulonglong2*>(tg + (bi * 8 + r) * ROW_B);
#pragma unroll
            for (int q = 0; q < 8; q++) {
                ulonglong2 bv = *reinterpret_cast<const ulonglong2*>(tg + (bj * 8 + q) * ROW_B);
#pragma unroll
                for (int r = 0; r < 8; r++) {
                    ffma2(acc[r * 8 + q], av[r].x, bv.x);
                    ffma2(acc[r * 8 + q], av[r].y, bv.y);
                }
            }
        }
        if (++stg == GSTAGES) { stg = 0; ph ^= 1; }
    }

#pragma unroll
    for (int p = 0; p < 64; p++) {
        float v = __uint_as_float((unsigned)acc[p]) +
                  __uint_as_float((unsigned)(acc[p] >> 32));
        v += __shfl_xor_sync(0xffffffffu, v, 16);
        v += __shfl_xor_sync(0xffffffffu, v, 8);
        v += __shfl_xor_sync(0xffffffffu, v, 4);
        v += __shfl_xor_sync(0xffffffffu, v, 2);
        v += __shfl_xor_sync(0xffffffffu, v, 1);
        if (lane == 0) g_Gpart[(b * NWARP1 + w) * 64 + p] = v;
    }
}

// ---------------- pass 1b: partials -> K -> coefficient table ----------------
__global__ __launch_bounds__(1024, 1)
void coef_kernel() {
    __shared__ float Gs[32][32];
    __shared__ float Ks[32][33];
    __shared__ float Ssh[32];
    const int tid = threadIdx.x;

    if (tid < NWARP1 * 64) {
        float s0 = 0.f, s1 = 0.f, s2 = 0.f, s3 = 0.f;
#pragma unroll 1
        for (int bb = 0; bb < NBLK1; bb += 4) {
            s0 += g_Gpart[(bb + 0) * (NWARP1 * 64) + tid];
            s1 += g_Gpart[(bb + 1) * (NWARP1 * 64) + tid];
            s2 += g_Gpart[(bb + 2) * (NWARP1 * 64) + tid];
            s3 += g_Gpart[(bb + 3) * (NWARP1 * 64) + tid];
        }
        float s = (s0 + s1) + (s2 + s3);
        int w = tid / 64, pr = tid % 64, r = pr / 8, q = pr % 8;
        Gs[c_TBI[w] * 8 + r][c_TBJ[w] * 8 + q] = s;
    }
    __syncthreads();
    {
        int i = tid >> 5, j = tid & 31;
        if ((i >> 3) > (j >> 3)) Gs[i][j] = Gs[j][i];
    }
    __syncthreads();
    {
        int i = tid >> 5, j = tid & 31;
        float d2 = Gs[i][i] + Gs[j][j] - 2.f * Gs[i][j];
        d2 = fmaxf(d2, 0.f);
        Ks[i][j] = expf(-0.5f * d2);
    }
    __syncthreads();
    if (tid < 32) {
        float s = 0.f;
        for (int j = 1; j < 32; j++) s += Ks[tid][j];
        Ssh[tid] = s;
    }
    __syncthreads();
    {
        int i = tid >> 5, j = tid & 31;
        float v = (j >= 1) ? (EPSV / (float)NPART) * Ks[i][j] : 0.f;
        if (j == i) v += 1.f - 3.f * EPSV * Ssh[i] / (float)NPART;
        g_Cd[j * 32 + i] = make_float2(v, v);   // [j][i], duplicated
    }
}

// ---------------- pass 2: out = C @ theta (R8 config) ----------------
// 2 CTAs/SM x 8 warps; warp w = k in [32w, 32w+32); lane = particle i.
__global__ __launch_bounds__(256, 2)
void apply_kernel(const float* __restrict__ W1, const float* __restrict__ b1,
                  const float* __restrict__ W2, const float* __restrict__ b2,
                  float* __restrict__ out) {
    extern __shared__ char sm[];
    const uint32_t sb = (uint32_t)__cvta_generic_to_shared(sm);
    const uint32_t mb_full = sb;
    ull* cs = reinterpret_cast<ull*>(sm + 64);    // 1024 x 8B coef [j*32+i]
    const int tid  = threadIdx.x;
    const int w    = tid >> 5;
    const int lane = tid & 31;

    if (tid == 0) {
#pragma unroll
        for (int s = 0; s < ASTAGES; s++) mbar_init(mb_full + s * 8, 1);
    }
    const ull* cg = reinterpret_cast<const ull*>(g_Cd);
    for (int idx = tid; idx < 1024; idx += 256) cs[idx] = cg[idx];
    __syncthreads();

    const int per = NCH / NBLK2, rem = NCH % NBLK2;
    const int b   = blockIdx.x;
    const int s0  = b * per + (b < rem ? b : rem);
    const int cnt = per + (b < rem ? 1 : 0);

    auto load_chunk = [&](int n) {                // producer warp, lane-parallel
        const int buf = n % ASTAGES;
        int stride, kl;
        const float* base = seg_base((s0 + n) * CH, W1, b1, W2, b2, stride, kl);
        const uint32_t full = mb_full + buf * 8;
        if (lane == 0) mbar_expect_tx(full, 32 * 1024u);
        __syncwarp();
        bulk_g2s(sb + AOFF + buf * ASTAGE_B + lane * ROW_B,
                 base + (size_t)lane * stride + kl, 1024u, full);
    };

    if (w == APW) {
        for (int n = 0; n < ASTAGES - 1 && n < cnt; n++) load_chunk(n);
    }

    const int sc = tid & 7;             // drain: unit-in-octet
    const int sr = tid >> 3;            // drain: particle row (0..31)

    int stg = 0, ph = 0;
    for (int it = 0; it < cnt; it++) {
        __syncthreads();
        if (w == APW) {
            int n = it + ASTAGES - 1;
            if (n < cnt) load_chunk(n);
        }
        mbar_wait(mb_full + stg * 8, ph);

        char* tb = sm + AOFF + stg * ASTAGE_B;
        const char* tbw = tb + w * 128;           // warp's 32-k window

        ull acc[16];
#pragma unroll
        for (int p = 0; p < 16; p++) acc[p] = 0ull;

#pragma unroll
        for (int j = 0; j < 32; j++) {
            const ulonglong2* pv = reinterpret_cast<const ulonglong2*>(tbw + j * ROW_B);
            ull c = cs[j * 32 + lane];
#pragma unroll
            for (int m = 0; m < 8; m += 2) {
                ulonglong2 v0 = pv[m], v1 = pv[m + 1];
                ffma2(acc[2 * m + 0], c, v0.x);
                ffma2(acc[2 * m + 1], c, v0.y);
                ffma2(acc[2 * m + 2], c, v1.x);
                ffma2(acc[2 * m + 3], c, v1.y);
            }
        }

        __syncthreads();                          // all reads of tb done
        {   // transpose: lane = particle row, XOR swizzle within octet
            ulonglong2* row = reinterpret_cast<ulonglong2*>(tb + lane * ROW_B);
#pragma unroll
            for (int m = 0; m < 8; m++) {
                int u = (w * 8 + m) ^ (lane & 7);
                row[u] = make_ulonglong2(acc[2 * m], acc[2 * m + 1]);
            }
        }
        __syncthreads();
        {   // drain: 8 threads per particle row, 128B-coalesced per octet
            const ulonglong2* row = reinterpret_cast<const ulonglong2*>(tb + sr * ROW_B);
            float* op = out + (size_t)sr * P_TOT + (size_t)(s0 + it) * CH;
#pragma unroll
            for (int t = 0; t < 8; t++) {
                int u = sc + 8 * t;
                ulonglong2 v = row[(u & ~7) + ((u & 7) ^ (sr & 7))];
                *reinterpret_cast<ulonglong2*>(op + 4 * u) = v;
            }
        }
        if (++stg == ASTAGES) { stg = 0; ph ^= 1; }
    }
}

// ---------------- launch ----------------
extern "C" void kernel_launch(void* const* d_in, const int* in_sizes, int n_in,
                              void* d_out, int out_size) {
    const float* W1 = (const float*)d_in[0];
    const float* b1 = (const float*)d_in[1];
    const float* W2 = (const float*)d_in[2];
    const float* b2 = (const float*)d_in[3];
    float* out = (float*)d_out;

    cudaFuncSetAttribute(gram_kernel,  cudaFuncAttributeMaxDynamicSharedMemorySize, GSMEM);
    cudaFuncSetAttribute(apply_kernel, cudaFuncAttributeMaxDynamicSharedMemorySize, ASMEM);

    gram_kernel<<<NBLK1, 320, GSMEM>>>(W1, b1, W2, b2);
    coef_kernel<<<1, 1024>>>();
    apply_kernel<<<NBLK2, 256, ASMEM>>>(W1, b1, W2, b2, out);
}

// round 12
// speedup vs baseline: 2.1713x; 2.1713x over previous
#include <cuda_runtime.h>
#include <cstdint>

typedef unsigned long long ull;

#define NPART 32
#define L0 (2048*1024)
#define L1 2048
#define L2 (256*2048)
#define L3 256
#define SEG_B0 (L0)
#define SEG_B1 (SEG_B0 + L1)
#define SEG_B2 (SEG_B1 + L2)
#define P_TOT  (SEG_B2 + L3)
#define EPSV 0.1f

#define GCH 512
#define GNCH 5125
#define GROW_B 2048
#define GSTAGES 3
#define GSTAGE_B (32*GROW_B)
#define GOFF 1024
#define GSMEM (GOFF + GSTAGES*GSTAGE_B)
#define NBLK1 148
#define NWARP1 10
#define GPW 9

#define ACH 256
#define ANCH (P_TOT/ACH)
#define AROW_B 1024
#define ASTAGES 3
#define ASTAGE_B (32*AROW_B)
#define AOFF 9216
#define ASMEM (AOFF + ASTAGES*ASTAGE_B)
#define NBLK2 296
#define APW 7

__device__ float  g_Gpart[NBLK1 * NWARP1 * 64];
__device__ float2 g_Cd[1024];

__constant__ int c_TBI[NWARP1] = {0,0,0,0,1,1,1,2,2,3};
__constant__ int c_TBJ[NWARP1] = {0,1,2,3,1,2,3,2,3,3};

__device__ __forceinline__ void ffma2(ull &d, ull a, ull b) {
    asm("fma.rn.f32x2 %0, %1, %2, %0;" : "+l"(d) : "l"(a), "l"(b));
}
__device__ __forceinline__ void mbar_init(uint32_t mbar, uint32_t cnt) {
    asm volatile("mbarrier.init.shared.b64 [%0], %1;" :: "r"(mbar), "r"(cnt) : "memory");
}
__device__ __forceinline__ void mbar_expect_tx(uint32_t mbar, uint32_t bytes) {
    asm volatile("mbarrier.arrive.expect_tx.shared.b64 _, [%0], %1;"
                 :: "r"(mbar), "r"(bytes) : "memory");
}
__device__ __forceinline__ void mbar_wait(uint32_t mbar, uint32_t phase) {
    asm volatile(
        "{\n\t.reg .pred P;\n\t"
        "WL_%=:\n\t"
        "mbarrier.try_wait.parity.acquire.cta.shared::cta.b64 P, [%0], %1, 0x989680;\n\t"
        "@!P bra WL_%=;\n\t}"
        :: "r"(mbar), "r"(phase) : "memory");
}
__device__ __forceinline__ void bulk_g2s(uint32_t dst, const void* src,
                                         uint32_t bytes, uint32_t mbar) {
    asm volatile(
        "cp.async.bulk.shared::cluster.global.mbarrier::complete_tx::bytes [%0], [%1], %2, [%3];"
        :: "r"(dst), "l"(src), "r"(bytes), "r"(mbar) : "memory");
}

__device__ __forceinline__ const float* seg_base(int k,
        const float* __restrict__ W1, const float* __restrict__ b1,
        const float* __restrict__ W2, const float* __restrict__ b2,
        int &stride, int &kl) {
    if (k < SEG_B0) { stride = L0; kl = k;          return W1; }
    if (k < SEG_B1) { stride = L1; kl = k - SEG_B0; return b1; }
    if (k < SEG_B2) { stride = L2; kl = k - SEG_B1; return W2; }
    stride = L3; kl = k - SEG_B2; return b2;
}

// ---------------- pass 1: Gram (R8-exact) ----------------
__global__ __launch_bounds__(320, 1)
void gram_kernel(const float* __restrict__ W1, const float* __restrict__ b1,
                 const float* __restrict__ W2, const float* __restrict__ b2) {
    extern __shared__ char sm[];
    const uint32_t sb = (uint32_t)__cvta_generic_to_shared(sm);
    const uint32_t mb_full = sb;
    const int tid  = threadIdx.x;
    const int w    = tid >> 5;
    const int lane = tid & 31;
    const int bi = c_TBI[w], bj = c_TBJ[w];

    const int per = GNCH / NBLK1, rem = GNCH % NBLK1;
    const int b   = blockIdx.x;
    const int c0  = b * per + (b < rem ? b : rem);
    const int cnt = per + (b < rem ? 1 : 0);

    if (tid == 0) {
#pragma unroll
        for (int s = 0; s < GSTAGES; s++) mbar_init(mb_full + s * 8, 1);
    }
    __syncthreads();

    auto load_chunk = [&](int n) {
        const int chunk = c0 + n;
        const int buf = n % GSTAGES;
        const uint32_t bytes = (chunk == GNCH - 1) ? 1024u : 2048u;
        int stride, kl;
        const float* base = seg_base(chunk * GCH, W1, b1, W2, b2, stride, kl);
        const uint32_t full = mb_full + buf * 8;
        if (lane == 0) mbar_expect_tx(full, bytes * 32);
        __syncwarp();
        bulk_g2s(sb + GOFF + buf * GSTAGE_B + lane * GROW_B,
                 base + (size_t)lane * stride + kl, bytes, full);
    };

    if (w == GPW) {
        for (int n = 0; n < GSTAGES - 1 && n < cnt; n++) load_chunk(n);
    }

    ull acc[64];
#pragma unroll
    for (int p = 0; p < 64; p++) acc[p] = 0ull;

    int stg = 0, ph = 0;
    for (int it = 0; it < cnt; it++) {
        __syncthreads();
        if (w == GPW) {
            int n = it + GSTAGES - 1;
            if (n < cnt) load_chunk(n);
        }
        mbar_wait(mb_full + stg * 8, ph);

        const char* tb = sm + GOFF + stg * GSTAGE_B;
        const int niter = (c0 + it == GNCH - 1) ? 2 : 4;
        for (int g = 0; g < niter; g++) {
            const char* tg = tb + g * 512 + lane * 16;
            ulonglong2 av[8];
#pragma unroll
            for (int r = 0; r < 8; r++)
                av[r] = *reinterpret_cast<const ulonglong2*>(tg + (bi * 8 + r) * GROW_B);
#pragma unroll
            for (int q = 0; q < 8; q++) {
                ulonglong2 bv = *reinterpret_cast<const ulonglong2*>(tg + (bj * 8 + q) * GROW_B);
#pragma unroll
                for (int r = 0; r < 8; r++) {
                    ffma2(acc[r * 8 + q], av[r].x, bv.x);
                    ffma2(acc[r * 8 + q], av[r].y, bv.y);
                }
            }
        }
        if (++stg == GSTAGES) { stg = 0; ph ^= 1; }
    }

#pragma unroll
    for (int p = 0; p < 64; p++) {
        float v = __uint_as_float((unsigned)acc[p]) +
                  __uint_as_float((unsigned)(acc[p] >> 32));
        v += __shfl_xor_sync(0xffffffffu, v, 16);
        v += __shfl_xor_sync(0xffffffffu, v, 8);
        v += __shfl_xor_sync(0xffffffffu, v, 4);
        v += __shfl_xor_sync(0xffffffffu, v, 2);
        v += __shfl_xor_sync(0xffffffffu, v, 1);
        if (lane == 0) g_Gpart[(b * NWARP1 + w) * 64 + p] = v;
    }
}

// ---------------- pass 1b ----------------
__global__ __launch_bounds__(1024, 1)
void coef_kernel() {
    __shared__ float Gs[32][32];
    __shared__ float Ks[32][33];
    __shared__ float Ssh[32];
    const int tid = threadIdx.x;

    if (tid < NWARP1 * 64) {
        float s0 = 0.f, s1 = 0.f, s2 = 0.f, s3 = 0.f;
#pragma unroll 1
        for (int bb = 0; bb < NBLK1; bb += 4) {
            s0 += g_Gpart[(bb + 0) * (NWARP1 * 64) + tid];
            s1 += g_Gpart[(bb + 1) * (NWARP1 * 64) + tid];
            s2 += g_Gpart[(bb + 2) * (NWARP1 * 64) + tid];
            s3 += g_Gpart[(bb + 3) * (NWARP1 * 64) + tid];
        }
        float s = (s0 + s1) + (s2 + s3);
        int w = tid / 64, pr = tid % 64, r = pr / 8, q = pr % 8;
        Gs[c_TBI[w] * 8 + r][c_TBJ[w] * 8 + q] = s;
    }
    __syncthreads();
    {
        int i = tid >> 5, j = tid & 31;
        if ((i >> 3) > (j >> 3)) Gs[i][j] = Gs[j][i];
    }
    __syncthreads();
    {
        int i = tid >> 5, j = tid & 31;
        float d2 = Gs[i][i] + Gs[j][j] - 2.f * Gs[i][j];
        d2 = fmaxf(d2, 0.f);
        Ks[i][j] = expf(-0.5f * d2);
    }
    __syncthreads();
    if (tid < 32) {
        float s = 0.f;
        for (int j = 1; j < 32; j++) s += Ks[tid][j];
        Ssh[tid] = s;
    }
    __syncthreads();
    {
        int i = tid >> 5, j = tid & 31;
        float v = (j >= 1) ? (EPSV / (float)NPART) * Ks[i][j] : 0.f;
        if (j == i) v += 1.f - 3.f * EPSV * Ssh[i] / (float)NPART;
        g_Cd[j * 32 + i] = make_float2(v, v);
    }
}

// ---------------- pass 2: out = C @ theta (j-pipelined) ----------------
__global__ __launch_bounds__(256, 2)
void apply_kernel(const float* __restrict__ W1, const float* __restrict__ b1,
                  const float* __restrict__ W2, const float* __restrict__ b2,
                  float* __restrict__ out) {
    extern __shared__ char sm[];
    const uint32_t sb = (uint32_t)__cvta_generic_to_shared(sm);
    const uint32_t mb_full = sb;
    ull* cs = reinterpret_cast<ull*>(sm + 64);
    const int tid  = threadIdx.x;
    const int w    = tid >> 5;
    const int lane = tid & 31;

    if (tid == 0) {
#pragma unroll
        for (int s = 0; s < ASTAGES; s++) mbar_init(mb_full + s * 8, 1);
    }
    const ull* cg = reinterpret_cast<const ull*>(g_Cd);
    for (int idx = tid; idx < 1024; idx += 256) cs[idx] = cg[idx];
    __syncthreads();

    const int per = ANCH / NBLK2, rem = ANCH % NBLK2;
    const int b   = blockIdx.x;
    const int s0  = b * per + (b < rem ? b : rem);
    const int cnt = per + (b < rem ? 1 : 0);

    auto load_chunk = [&](int n) {
        const int buf = n % ASTAGES;
        int stride, kl;
        const float* base = seg_base((s0 + n) * ACH, W1, b1, W2, b2, stride, kl);
        const uint32_t full = mb_full + buf * 8;
        if (lane == 0) mbar_expect_tx(full, 32 * 1024u);
        __syncwarp();
        bulk_g2s(sb + AOFF + buf * ASTAGE_B + lane * AROW_B,
                 base + (size_t)lane * stride + kl, 1024u, full);
    };

    if (w == APW) {
        for (int n = 0; n < ASTAGES - 1 && n < cnt; n++) load_chunk(n);
    }

    const int sc = tid & 7;
    const int sr = tid >> 3;

    int stg = 0, ph = 0;
    for (int it = 0; it < cnt; it++) {
        __syncthreads();
        if (w == APW) {
            int n = it + ASTAGES - 1;
            if (n < cnt) load_chunk(n);
        }
        mbar_wait(mb_full + stg * 8, ph);

        char* tb = sm + AOFF + stg * ASTAGE_B;
        const char* tbw = tb + w * 128;

        ull acc[16];
#pragma unroll
        for (int p = 0; p < 16; p++) acc[p] = 0ull;

        {   // software-pipelined j loop: prefetch j+1 window + coef
            const ulonglong2* p0 = reinterpret_cast<const ulonglong2*>(tbw);
            ulonglong2 n0 = p0[0], n1 = p0[1], n2 = p0[2], n3 = p0[3];
            ull cn = cs[lane];
#pragma unroll
            for (int j = 0; j < 32; j++) {
                ulonglong2 v0 = n0, v1 = n1, v2 = n2, v3 = n3;
                ull c = cn;
                if (j < 31) {
                    const ulonglong2* pn =
                        reinterpret_cast<const ulonglong2*>(tbw + (j + 1) * AROW_B);
                    n0 = pn[0]; n1 = pn[1]; n2 = pn[2]; n3 = pn[3];
                    cn = cs[(j + 1) * 32 + lane];
                }
                ffma2(acc[0],  c, v0.x);
                ffma2(acc[1],  c, v0.y);
                ffma2(acc[2],  c, v1.x);
                ffma2(acc[3],  c, v1.y);
                ffma2(acc[4],  c, v2.x);
                ffma2(acc[5],  c, v2.y);
                ffma2(acc[6],  c, v3.x);
                ffma2(acc[7],  c, v3.y);
            }
        }
        // NOTE: window is 128B = 8 ulonglong2; handle upper 4 via second pass
        {   // second half of the window (units 4..7), same pipeline
            const char* tbw2 = tbw + 64;
            const ulonglong2* p0 = reinterpret_cast<const ulonglong2*>(tbw2);
            ulonglong2 n0 = p0[0], n1 = p0[1], n2 = p0[2], n3 = p0[3];
            ull cn = cs[lane];
#pragma unroll
            for (int j = 0; j < 32; j++) {
                ulonglong2 v0 = n0, v1 = n1, v2 = n2, v3 = n3;
                ull c = cn;
                if (j < 31) {
                    const ulonglong2* pn =
                        reinterpret_cast<const ulonglong2*>(tbw2 + (j + 1) * AROW_B);
                    n0 = pn[0]; n1 = pn[1]; n2 = pn[2]; n3 = pn[3];
                    cn = cs[(j + 1) * 32 + lane];
                }
                ffma2(acc[8],  c, v0.x);
                ffma2(acc[9],  c, v0.y);
                ffma2(acc[10], c, v1.x);
                ffma2(acc[11], c, v1.y);
                ffma2(acc[12], c, v2.x);
                ffma2(acc[13], c, v2.y);
                ffma2(acc[14], c, v3.x);
                ffma2(acc[15], c, v3.y);
            }
        }

        __syncthreads();
        {   // transpose: lane = particle row, XOR swizzle within octet
            ulonglong2* row = reinterpret_cast<ulonglong2*>(tb + lane * AROW_B);
#pragma unroll
            for (int m = 0; m < 8; m++) {
                int u = (w * 8 + m) ^ (lane & 7);
                row[u] = make_ulonglong2(acc[2 * m], acc[2 * m + 1]);
            }
        }
        __syncthreads();
        {   // drain
            const ulonglong2* row = reinterpret_cast<const ulonglong2*>(tb + sr * AROW_B);
            float* op = out + (size_t)sr * P_TOT + (size_t)(s0 + it) * ACH;
#pragma unroll
            for (int t = 0; t < 8; t++) {
                int u = sc + 8 * t;
                ulonglong2 v = row[(u & ~7) + ((u & 7) ^ (sr & 7))];
                *reinterpret_cast<ulonglong2*>(op + 4 * u) = v;
            }
        }
        if (++stg == ASTAGES) { stg = 0; ph ^= 1; }
    }
}

extern "C" void kernel_launch(void* const* d_in, const int* in_sizes, int n_in,
                              void* d_out, int out_size) {
    const float* W1 = (const float*)d_in[0];
    const float* b1 = (const float*)d_in[1];
    const float* W2 = (const float*)d_in[2];
    const float* b2 = (const float*)d_in[3];
    float* out = (float*)d_out;

    cudaFuncSetAttribute(gram_kernel,  cudaFuncAttributeMaxDynamicSharedMemorySize, GSMEM);
    cudaFuncSetAttribute(apply_kernel, cudaFuncAttributeMaxDynamicSharedMemorySize, ASMEM);

    gram_kernel<<<NBLK1, 320, GSMEM>>>(W1, b1, W2, b2);
    coef_kernel<<<1, 1024>>>();
    apply_kernel<<<NBLK2, 256, ASMEM>>>(W1, b1, W2, b2, out);
}

// round 14
// speedup vs baseline: 2.3286x; 1.0725x over previous
#include <cuda_runtime.h>
#include <cstdint>

typedef unsigned long long ull;

// ---------------- problem constants ----------------
#define NPART 32
#define L0 (2048*1024)
#define L1 2048
#define L2 (256*2048)
#define L3 256
#define SEG_B0 (L0)              // 2097152
#define SEG_B1 (SEG_B0 + L1)     // 2099200
#define SEG_B2 (SEG_B1 + L2)     // 2623488
#define P_TOT  (SEG_B2 + L3)     // 2623744
#define EPSV 0.1f

// ---- gram: chunks of 512 k (last = 256 k), R8-exact ----
#define GCH 512
#define GNCH 5125
#define GROW_B 2048
#define GSTAGES 3
#define GSTAGE_B (32*GROW_B)     // 65536
#define GOFF 1024
#define GSMEM (GOFF + GSTAGES*GSTAGE_B)
#define NBLK1 148
#define NWARP1 10
#define GPW 9

// ---- apply: 256-k chunks (10249 exact); padded rows; TMA-store drain ----
#define ACH 256
#define ANCH (P_TOT/ACH)         // 10249
#define AROW_B 1040              // 1024 + 16 pad: bank-rotates rows, keeps 16B align
#define ASTAGES 3
#define ASTAGE_B (32*AROW_B)     // 33280
#define AOFF 9216                // mbar(64) + coef table(8KB)
#define ASMEM (AOFF + ASTAGES*ASTAGE_B)   // 109056 -> 2 CTAs/SM
#define NBLK2 296
#define APW 7

// ---------------- scratch ----------------
__device__ float  g_Gpart[NBLK1 * NWARP1 * 64];
__device__ float2 g_Cd[1024];        // g_Cd[j*32+i] = (C[i][j], C[i][j])

__constant__ int c_TBI[NWARP1] = {0,0,0,0,1,1,1,2,2,3};
__constant__ int c_TBJ[NWARP1] = {0,1,2,3,1,2,3,2,3,3};

// ---------------- PTX helpers ----------------
__device__ __forceinline__ void ffma2(ull &d, ull a, ull b) {
    asm("fma.rn.f32x2 %0, %1, %2, %0;" : "+l"(d) : "l"(a), "l"(b));
}
__device__ __forceinline__ void mbar_init(uint32_t mbar, uint32_t cnt) {
    asm volatile("mbarrier.init.shared.b64 [%0], %1;" :: "r"(mbar), "r"(cnt) : "memory");
}
__device__ __forceinline__ void mbar_expect_tx(uint32_t mbar, uint32_t bytes) {
    asm volatile("mbarrier.arrive.expect_tx.shared.b64 _, [%0], %1;"
                 :: "r"(mbar), "r"(bytes) : "memory");
}
__device__ __forceinline__ void mbar_wait(uint32_t mbar, uint32_t phase) {
    asm volatile(
        "{\n\t.reg .pred P;\n\t"
        "WL_%=:\n\t"
        "mbarrier.try_wait.parity.acquire.cta.shared::cta.b64 P, [%0], %1, 0x989680;\n\t"
        "@!P bra WL_%=;\n\t}"
        :: "r"(mbar), "r"(phase) : "memory");
}
__device__ __forceinline__ void bulk_g2s(uint32_t dst, const void* src,
                                         uint32_t bytes, uint32_t mbar) {
    asm volatile(
        "cp.async.bulk.shared::cluster.global.mbarrier::complete_tx::bytes [%0], [%1], %2, [%3];"
        :: "r"(dst), "l"(src), "r"(bytes), "r"(mbar) : "memory");
}
__device__ __forceinline__ void bulk_s2g(void* dst, uint32_t src, uint32_t bytes) {
    asm volatile(
        "cp.async.bulk.global.shared::cta.bulk_group [%0], [%1], %2;"
        :: "l"(dst), "r"(src), "r"(bytes) : "memory");
}
__device__ __forceinline__ void bulk_commit() {
    asm volatile("cp.async.bulk.commit_group;" ::: "memory");
}
__device__ __forceinline__ void bulk_wait_read0() {
    asm volatile("cp.async.bulk.wait_group.read 0;" ::: "memory");
}
__device__ __forceinline__ void bulk_wait_all0() {
    asm volatile("cp.async.bulk.wait_group 0;" ::: "memory");
}
__device__ __forceinline__ void fence_async() {
    asm volatile("fence.proxy.async.shared::cta;" ::: "memory");
}

__device__ __forceinline__ const float* seg_base(int k,
        const float* __restrict__ W1, const float* __restrict__ b1,
        const float* __restrict__ W2, const float* __restrict__ b2,
        int &stride, int &kl) {
    if (k < SEG_B0) { stride = L0; kl = k;          return W1; }
    if (k < SEG_B1) { stride = L1; kl = k - SEG_B0; return b1; }
    if (k < SEG_B2) { stride = L2; kl = k - SEG_B1; return W2; }
    stride = L3; kl = k - SEG_B2; return b2;
}

// ---------------- pass 1: Gram (R8-exact) ----------------
__global__ __launch_bounds__(320, 1)
void gram_kernel(const float* __restrict__ W1, const float* __restrict__ b1,
                 const float* __restrict__ W2, const float* __restrict__ b2) {
    extern __shared__ char sm[];
    const uint32_t sb = (uint32_t)__cvta_generic_to_shared(sm);
    const uint32_t mb_full = sb;
    const int tid  = threadIdx.x;
    const int w    = tid >> 5;
    const int lane = tid & 31;
    const int bi = c_TBI[w], bj = c_TBJ[w];

    const int per = GNCH / NBLK1, rem = GNCH % NBLK1;
    const int b   = blockIdx.x;
    const int c0  = b * per + (b < rem ? b : rem);
    const int cnt = per + (b < rem ? 1 : 0);

    if (tid == 0) {
#pragma unroll
        for (int s = 0; s < GSTAGES; s++) mbar_init(mb_full + s * 8, 1);
    }
    __syncthreads();

    auto load_chunk = [&](int n) {
        const int chunk = c0 + n;
        const int buf = n % GSTAGES;
        const uint32_t bytes = (chunk == GNCH - 1) ? 1024u : 2048u;
        int stride, kl;
        const float* base = seg_base(chunk * GCH, W1, b1, W2, b2, stride, kl);
        const uint32_t full = mb_full + buf * 8;
        if (lane == 0) mbar_expect_tx(full, bytes * 32);
        __syncwarp();
        bulk_g2s(sb + GOFF + buf * GSTAGE_B + lane * GROW_B,
                 base + (size_t)lane * stride + kl, bytes, full);
    };

    if (w == GPW) {
        for (int n = 0; n < GSTAGES - 1 && n < cnt; n++) load_chunk(n);
    }

    ull acc[64];
#pragma unroll
    for (int p = 0; p < 64; p++) acc[p] = 0ull;

    int stg = 0, ph = 0;
    for (int it = 0; it < cnt; it++) {
        __syncthreads();
        if (w == GPW) {
            int n = it + GSTAGES - 1;
            if (n < cnt) load_chunk(n);
        }
        mbar_wait(mb_full + stg * 8, ph);

        const char* tb = sm + GOFF + stg * GSTAGE_B;
        const int niter = (c0 + it == GNCH - 1) ? 2 : 4;
        for (int g = 0; g < niter; g++) {
            const char* tg = tb + g * 512 + lane * 16;
            ulonglong2 av[8];
#pragma unroll
            for (int r = 0; r < 8; r++)
                av[r] = *reinterpret_cast<const ulonglong2*>(tg + (bi * 8 + r) * GROW_B);
#pragma unroll
            for (int q = 0; q < 8; q++) {
                ulonglong2 bv = *reinterpret_cast<const ulonglong2*>(tg + (bj * 8 + q) * GROW_B);
#pragma unroll
                for (int r = 0; r < 8; r++) {
                    ffma2(acc[r * 8 + q], av[r].x, bv.x);
                    ffma2(acc[r * 8 + q], av[r].y, bv.y);
                }
            }
        }
        if (++stg == GSTAGES) { stg = 0; ph ^= 1; }
    }

#pragma unroll
    for (int p = 0; p < 64; p++) {
        float v = __uint_as_float((unsigned)acc[p]) +
                  __uint_as_float((unsigned)(acc[p] >> 32));
        v += __shfl_xor_sync(0xffffffffu, v, 16);
        v += __shfl_xor_sync(0xffffffffu, v, 8);
        v += __shfl_xor_sync(0xffffffffu, v, 4);
        v += __shfl_xor_sync(0xffffffffu, v, 2);
        v += __shfl_xor_sync(0xffffffffu, v, 1);
        if (lane == 0) g_Gpart[(b * NWARP1 + w) * 64 + p] = v;
    }
}

// ---------------- pass 1b: partials -> K -> coefficient table ----------------
__global__ __launch_bounds__(1024, 1)
void coef_kernel() {
    __shared__ float Gs[32][32];
    __shared__ float Ks[32][33];
    __shared__ float Ssh[32];
    const int tid = threadIdx.x;

    if (tid < NWARP1 * 64) {
        float s0 = 0.f, s1 = 0.f, s2 = 0.f, s3 = 0.f;
#pragma unroll 1
        for (int bb = 0; bb < NBLK1; bb += 4) {
            s0 += g_Gpart[(bb + 0) * (NWARP1 * 64) + tid];
            s1 += g_Gpart[(bb + 1) * (NWARP1 * 64) + tid];
            s2 += g_Gpart[(bb + 2) * (NWARP1 * 64) + tid];
            s3 += g_Gpart[(bb + 3) * (NWARP1 * 64) + tid];
        }
        float s = (s0 + s1) + (s2 + s3);
        int w = tid / 64, pr = tid % 64, r = pr / 8, q = pr % 8;
        Gs[c_TBI[w] * 8 + r][c_TBJ[w] * 8 + q] = s;
    }
    __syncthreads();
    {
        int i = tid >> 5, j = tid & 31;
        if ((i >> 3) > (j >> 3)) Gs[i][j] = Gs[j][i];
    }
    __syncthreads();
    {
        int i = tid >> 5, j = tid & 31;
        float d2 = Gs[i][i] + Gs[j][j] - 2.f * Gs[i][j];
        d2 = fmaxf(d2, 0.f);
        Ks[i][j] = expf(-0.5f * d2);
    }
    __syncthreads();
    if (tid < 32) {
        float s = 0.f;
        for (int j = 1; j < 32; j++) s += Ks[tid][j];
        Ssh[tid] = s;
    }
    __syncthreads();
    {
        int i = tid >> 5, j = tid & 31;
        float v = (j >= 1) ? (EPSV / (float)NPART) * Ks[i][j] : 0.f;
        if (j == i) v += 1.f - 3.f * EPSV * Ssh[i] / (float)NPART;
        g_Cd[j * 32 + i] = make_float2(v, v);
    }
}

// ---------------- pass 2: out = C @ theta (TMA-store drain) ----------------
// 2 CTAs/SM x 8 warps; warp w = k in [32w, 32w+32); lane = particle i.
// Rows padded to 1040B -> unswizzled transpose is conflict-free and rows stay
// in logical byte order, so the producer warp drains them with bulk S2G.
__global__ __launch_bounds__(256, 2)
void apply_kernel(const float* __restrict__ W1, const float* __restrict__ b1,
                  const float* __restrict__ W2, const float* __restrict__ b2,
                  float* __restrict__ out) {
    extern __shared__ char sm[];
    const uint32_t sb = (uint32_t)__cvta_generic_to_shared(sm);
    const uint32_t mb_full = sb;
    ull* cs = reinterpret_cast<ull*>(sm + 64);    // 1024 x 8B coef [j*32+i]
    const int tid  = threadIdx.x;
    const int w    = tid >> 5;
    const int lane = tid & 31;

    if (tid == 0) {
#pragma unroll
        for (int s = 0; s < ASTAGES; s++) mbar_init(mb_full + s * 8, 1);
    }
    const ull* cg = reinterpret_cast<const ull*>(g_Cd);
    for (int idx = tid; idx < 1024; idx += 256) cs[idx] = cg[idx];
    __syncthreads();

    const int per = ANCH / NBLK2, rem = ANCH % NBLK2;
    const int b   = blockIdx.x;
    const int s0  = b * per + (b < rem ? b : rem);
    const int cnt = per + (b < rem ? 1 : 0);

    auto load_chunk = [&](int n) {                // producer warp, lane-parallel
        const int buf = n % ASTAGES;
        int stride, kl;
        const float* base = seg_base((s0 + n) * ACH, W1, b1, W2, b2, stride, kl);
        const uint32_t full = mb_full + buf * 8;
        if (lane == 0) mbar_expect_tx(full, 32 * 1024u);
        __syncwarp();
        bulk_g2s(sb + AOFF + buf * ASTAGE_B + lane * AROW_B,
                 base + (size_t)lane * stride + kl, 1024u, full);
    };

    if (w == APW) {
        for (int n = 0; n < ASTAGES - 1 && n < cnt; n++) load_chunk(n);
    }

    int stg = 0, ph = 0;
    for (int it = 0; it < cnt; it++) {
        __syncthreads();
        if (w == APW) {
            int n = it + ASTAGES - 1;
            if (n < cnt) {
                bulk_wait_read0();      // our store of this buffer has read smem
                load_chunk(n);
            }
        }
        mbar_wait(mb_full + stg * 8, ph);

        char* tb = sm + AOFF + stg * ASTAGE_B;
        const char* tbw = tb + w * 128;           // warp's 32-k window

        ull acc[16];
#pragma unroll
        for (int p = 0; p < 16; p++) acc[p] = 0ull;

#pragma unroll
        for (int j = 0; j < 32; j++) {
            const ulonglong2* pv = reinterpret_cast<const ulonglong2*>(tbw + j * AROW_B);
            ull c = cs[j * 32 + lane];
#pragma unroll
            for (int m = 0; m < 8; m += 2) {
                ulonglong2 v0 = pv[m], v1 = pv[m + 1];
                ffma2(acc[2 * m + 0], c, v0.x);
                ffma2(acc[2 * m + 1], c, v0.y);
                ffma2(acc[2 * m + 2], c, v1.x);
                ffma2(acc[2 * m + 3], c, v1.y);
            }
        }

        __syncthreads();                          // all reads of tb done
        {   // transpose: lane = particle row; no swizzle (1040B rows rotate banks)
            ulonglong2* row = reinterpret_cast<ulonglong2*>(tb + lane * AROW_B);
#pragma unroll
            for (int m = 0; m < 8; m++)
                row[w * 8 + m] = make_ulonglong2(acc[2 * m], acc[2 * m + 1]);
        }
        __syncthreads();
        if (w == APW) {                           // drain: 1KB contiguous row per lane
            fence_async();
            bulk_s2g(out + (size_t)lane * P_TOT + (size_t)(s0 + it) * ACH,
                     sb + AOFF + stg * ASTAGE_B + lane * AROW_B, 1024u);
            bulk_commit();
        }
        if (++stg == ASTAGES) { stg = 0; ph ^= 1; }
    }
    if (w == APW) bulk_wait_all0();               // stores land before kernel exit
}

// ---------------- launch ----------------
extern "C" void kernel_launch(void* const* d_in, const int* in_sizes, int n_in,
                              void* d_out, int out_size) {
    const float* W1 = (const float*)d_in[0];
    const float* b1 = (const float*)d_in[1];
    const float* W2 = (const float*)d_in[2];
    const float* b2 = (const float*)d_in[3];
    float* out = (float*)d_out;

    cudaFuncSetAttribute(gram_kernel,  cudaFuncAttributeMaxDynamicSharedMemorySize, GSMEM);
    cudaFuncSetAttribute(apply_kernel, cudaFuncAttributeMaxDynamicSharedMemorySize, ASMEM);

    gram_kernel<<<NBLK1, 320, GSMEM>>>(W1, b1, W2, b2);
    coef_kernel<<<1, 1024>>>();
    apply_kernel<<<NBLK2, 256, ASMEM>>>(W1, b1, W2, b2, out);
}

// round 15
// speedup vs baseline: 2.3510x; 1.0096x over previous
#include <cuda_runtime.h>
#include <cstdint>

typedef unsigned long long ull;

// ---------------- problem constants ----------------
#define NPART 32
#define L0 (2048*1024)
#define L1 2048
#define L2 (256*2048)
#define L3 256
#define SEG_B0 (L0)              // 2097152
#define SEG_B1 (SEG_B0 + L1)     // 2099200
#define SEG_B2 (SEG_B1 + L2)     // 2623488
#define P_TOT  (SEG_B2 + L3)     // 2623744
#define EPSV 0.1f

// ---- gram: chunks of 512 k (last = 256 k), R8-exact ----
#define GCH 512
#define GNCH 5125
#define GROW_B 2048
#define GSTAGES 3
#define GSTAGE_B (32*GROW_B)     // 65536
#define GOFF 1024
#define GSMEM (GOFF + GSTAGES*GSTAGE_B)
#define NBLK1 148
#define NWARP1 10
#define GPW 9

// ---- apply: 256-k chunks (10249 exact); padded rows; overlapped TMA drain ----
#define ACH 256
#define ANCH (P_TOT/ACH)         // 10249
#define AROW_B 1040              // 1024 + 16 pad (conflict-free transpose, TMA-drainable)
#define ASTAGES 3
#define ASTAGE_B (32*AROW_B)     // 33280
#define AOFF 9216                // mbar(64) + coef table(8KB)
#define ASMEM (AOFF + ASTAGES*ASTAGE_B)   // 109056 -> 2 CTAs/SM
#define NBLK2 296
#define APW 7

// ---------------- scratch ----------------
__device__ float  g_Gpart[NBLK1 * NWARP1 * 64];
__device__ float2 g_Cd[1024];        // g_Cd[j*32+i] = (C[i][j], C[i][j])

__constant__ int c_TBI[NWARP1] = {0,0,0,0,1,1,1,2,2,3};
__constant__ int c_TBJ[NWARP1] = {0,1,2,3,1,2,3,2,3,3};

// ---------------- PTX helpers ----------------
__device__ __forceinline__ void ffma2(ull &d, ull a, ull b) {
    asm("fma.rn.f32x2 %0, %1, %2, %0;" : "+l"(d) : "l"(a), "l"(b));
}
__device__ __forceinline__ void mbar_init(uint32_t mbar, uint32_t cnt) {
    asm volatile("mbarrier.init.shared.b64 [%0], %1;" :: "r"(mbar), "r"(cnt) : "memory");
}
__device__ __forceinline__ void mbar_expect_tx(uint32_t mbar, uint32_t bytes) {
    asm volatile("mbarrier.arrive.expect_tx.shared.b64 _, [%0], %1;"
                 :: "r"(mbar), "r"(bytes) : "memory");
}
__device__ __forceinline__ void mbar_wait(uint32_t mbar, uint32_t phase) {
    asm volatile(
        "{\n\t.reg .pred P;\n\t"
        "WL_%=:\n\t"
        "mbarrier.try_wait.parity.acquire.cta.shared::cta.b64 P, [%0], %1, 0x989680;\n\t"
        "@!P bra WL_%=;\n\t}"
        :: "r"(mbar), "r"(phase) : "memory");
}
__device__ __forceinline__ void bulk_g2s(uint32_t dst, const void* src,
                                         uint32_t bytes, uint32_t mbar) {
    asm volatile(
        "cp.async.bulk.shared::cluster.global.mbarrier::complete_tx::bytes [%0], [%1], %2, [%3];"
        :: "r"(dst), "l"(src), "r"(bytes), "r"(mbar) : "memory");
}
__device__ __forceinline__ void bulk_s2g(void* dst, uint32_t src, uint32_t bytes) {
    asm volatile(
        "cp.async.bulk.global.shared::cta.bulk_group [%0], [%1], %2;"
        :: "l"(dst), "r"(src), "r"(bytes) : "memory");
}
__device__ __forceinline__ void bulk_commit() {
    asm volatile("cp.async.bulk.commit_group;" ::: "memory");
}
__device__ __forceinline__ void bulk_wait_read0() {
    asm volatile("cp.async.bulk.wait_group.read 0;" ::: "memory");
}
__device__ __forceinline__ void bulk_wait_all0() {
    asm volatile("cp.async.bulk.wait_group 0;" ::: "memory");
}
__device__ __forceinline__ void fence_async() {
    asm volatile("fence.proxy.async.shared::cta;" ::: "memory");
}

__device__ __forceinline__ const float* seg_base(int k,
        const float* __restrict__ W1, const float* __restrict__ b1,
        const float* __restrict__ W2, const float* __restrict__ b2,
        int &stride, int &kl) {
    if (k < SEG_B0) { stride = L0; kl = k;          return W1; }
    if (k < SEG_B1) { stride = L1; kl = k - SEG_B0; return b1; }
    if (k < SEG_B2) { stride = L2; kl = k - SEG_B1; return W2; }
    stride = L3; kl = k - SEG_B2; return b2;
}

// ---------------- pass 1: Gram (R8-exact) ----------------
__global__ __launch_bounds__(320, 1)
void gram_kernel(const float* __restrict__ W1, const float* __restrict__ b1,
                 const float* __restrict__ W2, const float* __restrict__ b2) {
    extern __shared__ char sm[];
    const uint32_t sb = (uint32_t)__cvta_generic_to_shared(sm);
    const uint32_t mb_full = sb;
    const int tid  = threadIdx.x;
    const int w    = tid >> 5;
    const int lane = tid & 31;
    const int bi = c_TBI[w], bj = c_TBJ[w];

    const int per = GNCH / NBLK1, rem = GNCH % NBLK1;
    const int b   = blockIdx.x;
    const int c0  = b * per + (b < rem ? b : rem);
    const int cnt = per + (b < rem ? 1 : 0);

    if (tid == 0) {
#pragma unroll
        for (int s = 0; s < GSTAGES; s++) mbar_init(mb_full + s * 8, 1);
    }
    __syncthreads();

    auto load_chunk = [&](int n) {
        const int chunk = c0 + n;
        const int buf = n % GSTAGES;
        const uint32_t bytes = (chunk == GNCH - 1) ? 1024u : 2048u;
        int stride, kl;
        const float* base = seg_base(chunk * GCH, W1, b1, W2, b2, stride, kl);
        const uint32_t full = mb_full + buf * 8;
        if (lane == 0) mbar_expect_tx(full, bytes * 32);
        __syncwarp();
        bulk_g2s(sb + GOFF + buf * GSTAGE_B + lane * GROW_B,
                 base + (size_t)lane * stride + kl, bytes, full);
    };

    if (w == GPW) {
        for (int n = 0; n < GSTAGES - 1 && n < cnt; n++) load_chunk(n);
    }

    ull acc[64];
#pragma unroll
    for (int p = 0; p < 64; p++) acc[p] = 0ull;

    int stg = 0, ph = 0;
    for (int it = 0; it < cnt; it++) {
        __syncthreads();
        if (w == GPW) {
            int n = it + GSTAGES - 1;
            if (n < cnt) load_chunk(n);
        }
        mbar_wait(mb_full + stg * 8, ph);

        const char* tb = sm + GOFF + stg * GSTAGE_B;
        const int niter = (c0 + it == GNCH - 1) ? 2 : 4;
        for (int g = 0; g < niter; g++) {
            const char* tg = tb + g * 512 + lane * 16;
            ulonglong2 av[8];
#pragma unroll
            for (int r = 0; r < 8; r++)
                av[r] = *reinterpret_cast<const ulonglong2*>(tg + (bi * 8 + r) * GROW_B);
#pragma unroll
            for (int q = 0; q < 8; q++) {
                ulonglong2 bv = *reinterpret_cast<const ulonglong2*>(tg + (bj * 8 + q) * GROW_B);
#pragma unroll
                for (int r = 0; r < 8; r++) {
                    ffma2(acc[r * 8 + q], av[r].x, bv.x);
                    ffma2(acc[r * 8 + q], av[r].y, bv.y);
                }
            }
        }
        if (++stg == GSTAGES) { stg = 0; ph ^= 1; }
    }

#pragma unroll
    for (int p = 0; p < 64; p++) {
        float v = __uint_as_float((unsigned)acc[p]) +
                  __uint_as_float((unsigned)(acc[p] >> 32));
        v += __shfl_xor_sync(0xffffffffu, v, 16);
        v += __shfl_xor_sync(0xffffffffu, v, 8);
        v += __shfl_xor_sync(0xffffffffu, v, 4);
        v += __shfl_xor_sync(0xffffffffu, v, 2);
        v += __shfl_xor_sync(0xffffffffu, v, 1);
        if (lane == 0) g_Gpart[(b * NWARP1 + w) * 64 + p] = v;
    }
}

// ---------------- pass 1b: partials -> K -> coefficient table ----------------
__global__ __launch_bounds__(1024, 1)
void coef_kernel() {
    __shared__ float Gs[32][32];
    __shared__ float Ks[32][33];
    __shared__ float Ssh[32];
    const int tid = threadIdx.x;

    if (tid < NWARP1 * 64) {
        float s0 = 0.f, s1 = 0.f, s2 = 0.f, s3 = 0.f;
#pragma unroll 1
        for (int bb = 0; bb < NBLK1; bb += 4) {
            s0 += g_Gpart[(bb + 0) * (NWARP1 * 64) + tid];
            s1 += g_Gpart[(bb + 1) * (NWARP1 * 64) + tid];
            s2 += g_Gpart[(bb + 2) * (NWARP1 * 64) + tid];
            s3 += g_Gpart[(bb + 3) * (NWARP1 * 64) + tid];
        }
        float s = (s0 + s1) + (s2 + s3);
        int w = tid / 64, pr = tid % 64, r = pr / 8, q = pr % 8;
        Gs[c_TBI[w] * 8 + r][c_TBJ[w] * 8 + q] = s;
    }
    __syncthreads();
    {
        int i = tid >> 5, j = tid & 31;
        if ((i >> 3) > (j >> 3)) Gs[i][j] = Gs[j][i];
    }
    __syncthreads();
    {
        int i = tid >> 5, j = tid & 31;
        float d2 = Gs[i][i] + Gs[j][j] - 2.f * Gs[i][j];
        d2 = fmaxf(d2, 0.f);
        Ks[i][j] = expf(-0.5f * d2);
    }
    __syncthreads();
    if (tid < 32) {
        float s = 0.f;
        for (int j = 1; j < 32; j++) s += Ks[tid][j];
        Ssh[tid] = s;
    }
    __syncthreads();
    {
        int i = tid >> 5, j = tid & 31;
        float v = (j >= 1) ? (EPSV / (float)NPART) * Ks[i][j] : 0.f;
        if (j == i) v += 1.f - 3.f * EPSV * Ssh[i] / (float)NPART;
        g_Cd[j * 32 + i] = make_float2(v, v);
    }
}

// ---------------- pass 2: out = C @ theta (overlapped TMA drain) ----------------
// 2 CTAs/SM x 8 warps; warp w = k in [32w, 32w+32); lane = particle i.
// Iteration it: top sync; producer drains buf (it-1)%3 (prev transposed output)
// via bulk S2G, waits the read, reloads the SAME buf with chunk it+2 — all while
// the other warps compute chunk it from buf it%3 (its load completed at it-2).
__global__ __launch_bounds__(256, 2)
void apply_kernel(const float* __restrict__ W1, const float* __restrict__ b1,
                  const float* __restrict__ W2, const float* __restrict__ b2,
                  float* __restrict__ out) {
    extern __shared__ char sm[];
    const uint32_t sb = (uint32_t)__cvta_generic_to_shared(sm);
    const uint32_t mb_full = sb;
    ull* cs = reinterpret_cast<ull*>(sm + 64);    // 1024 x 8B coef [j*32+i]
    const int tid  = threadIdx.x;
    const int w    = tid >> 5;
    const int lane = tid & 31;

    if (tid == 0) {
#pragma unroll
        for (int s = 0; s < ASTAGES; s++) mbar_init(mb_full + s * 8, 1);
    }
    const ull* cg = reinterpret_cast<const ull*>(g_Cd);
    for (int idx = tid; idx < 1024; idx += 256) cs[idx] = cg[idx];
    __syncthreads();

    const int per = ANCH / NBLK2, rem = ANCH % NBLK2;
    const int b   = blockIdx.x;
    const int s0  = b * per + (b < rem ? b : rem);
    const int cnt = per + (b < rem ? 1 : 0);

    auto load_chunk = [&](int n) {                // producer warp, lane-parallel
        const int buf = n % ASTAGES;
        int stride, kl;
        const float* base = seg_base((s0 + n) * ACH, W1, b1, W2, b2, stride, kl);
        const uint32_t full = mb_full + buf * 8;
        if (lane == 0) mbar_expect_tx(full, 32 * 1024u);
        __syncwarp();
        bulk_g2s(sb + AOFF + buf * ASTAGE_B + lane * AROW_B,
                 base + (size_t)lane * stride + kl, 1024u, full);
    };

    if (w == APW) {
        for (int n = 0; n < ASTAGES - 1 && n < cnt; n++) load_chunk(n);
    }

    int stg = 0, ph = 0;
    for (int it = 0; it < cnt; it++) {
        __syncthreads();   // transposed output of it-1 visible; buffer reads of it-1 done
        if (w == APW) {
            if (it > 0) {  // drain buf (it-1)%3 : 1KB contiguous row per lane
                const int dstg = (it - 1) % ASTAGES;
                fence_async();
                bulk_s2g(out + (size_t)lane * P_TOT + (size_t)(s0 + it - 1) * ACH,
                         sb + AOFF + dstg * ASTAGE_B + lane * AROW_B, 1024u);
                bulk_commit();
            }
            int n = it + ASTAGES - 1;
            if (n < cnt) {
                bulk_wait_read0();   // drain has read the buffer it reuses
                load_chunk(n);
            }
        }
        mbar_wait(mb_full + stg * 8, ph);

        char* tb = sm + AOFF + stg * ASTAGE_B;
        const char* tbw = tb + w * 128;           // warp's 32-k window

        ull acc[16];
#pragma unroll
        for (int p = 0; p < 16; p++) acc[p] = 0ull;

#pragma unroll
        for (int j = 0; j < 32; j++) {
            const ulonglong2* pv = reinterpret_cast<const ulonglong2*>(tbw + j * AROW_B);
            ull c = cs[j * 32 + lane];
#pragma unroll
            for (int m = 0; m < 8; m += 2) {
                ulonglong2 v0 = pv[m], v1 = pv[m + 1];
                ffma2(acc[2 * m + 0], c, v0.x);
                ffma2(acc[2 * m + 1], c, v0.y);
                ffma2(acc[2 * m + 2], c, v1.x);
                ffma2(acc[2 * m + 3], c, v1.y);
            }
        }

        __syncthreads();                          // all reads of tb done
        {   // transpose in place: lane = particle row (1040B rows: conflict-free)
            ulonglong2* row = reinterpret_cast<ulonglong2*>(tb + lane * AROW_B);
#pragma unroll
            for (int m = 0; m < 8; m++)
                row[w * 8 + m] = make_ulonglong2(acc[2 * m], acc[2 * m + 1]);
        }
        if (++stg == ASTAGES) { stg = 0; ph ^= 1; }
    }

    __syncthreads();                              // final transposed buffer visible
    if (w == APW && cnt > 0) {                    // drain last chunk
        const int dstg = (cnt - 1) % ASTAGES;
        fence_async();
        bulk_s2g(out + (size_t)lane * P_TOT + (size_t)(s0 + cnt - 1) * ACH,
                 sb + AOFF + dstg * ASTAGE_B + lane * AROW_B, 1024u);
        bulk_commit();
        bulk_wait_all0();                         // stores land before exit
    }
}

// ---------------- launch ----------------
extern "C" void kernel_launch(void* const* d_in, const int* in_sizes, int n_in,
                              void* d_out, int out_size) {
    const float* W1 = (const float*)d_in[0];
    const float* b1 = (const float*)d_in[1];
    const float* W2 = (const float*)d_in[2];
    const float* b2 = (const float*)d_in[3];
    float* out = (float*)d_out;

    cudaFuncSetAttribute(gram_kernel,  cudaFuncAttributeMaxDynamicSharedMemorySize, GSMEM);
    cudaFuncSetAttribute(apply_kernel, cudaFuncAttributeMaxDynamicSharedMemorySize, ASMEM);

    gram_kernel<<<NBLK1, 320, GSMEM>>>(W1, b1, W2, b2);
    coef_kernel<<<1, 1024>>>();
    apply_kernel<<<NBLK2, 256, ASMEM>>>(W1, b1, W2, b2, out);
}

// round 16
// speedup vs baseline: 3.0180x; 1.2837x over previous
#include <cuda_runtime.h>
#include <cstdint>

typedef unsigned long long ull;

// ---------------- problem constants ----------------
#define NPART 32
#define L0 (2048*1024)
#define L1 2048
#define L2 (256*2048)
#define L3 256
#define SEG_B0 (L0)              // 2097152
#define SEG_B1 (SEG_B0 + L1)     // 2099200
#define SEG_B2 (SEG_B1 + L2)     // 2623488
#define P_TOT  (SEG_B2 + L3)     // 2623744
#define EPSV 0.1f

// ---- gram: chunks of 512 k (last = 256 k), R8-exact ----
#define GCH 512
#define GNCH 5125
#define GROW_B 2048
#define GSTAGES 3
#define GSTAGE_B (32*GROW_B)     // 65536
#define GOFF 1024
#define GSMEM (GOFF + GSTAGES*GSTAGE_B)
#define NBLK1 148
#define NWARP1 10
#define GPW 9

// ---- apply: 256-k chunks; padded rows; spread/multicast compute mapping ----
#define ACH 256
#define ANCH (P_TOT/ACH)         // 10249
#define AROW_B 1040              // 1024 + 16 pad
#define ASTAGES 3
#define ASTAGE_B (32*AROW_B)     // 33280
#define AOFF 9216                // mbar(64) + coef table(4KB) + slack
#define ASMEM (AOFF + ASTAGES*ASTAGE_B)   // 109056 -> 2 CTAs/SM
#define NBLK2 296
#define APW 7

// ---------------- scratch ----------------
__device__ float g_Gpart[NBLK1 * NWARP1 * 64];
__device__ float g_Cf[1024];         // g_Cf[j*32+i] = C[i][j] (float)

__constant__ int c_TBI[NWARP1] = {0,0,0,0,1,1,1,2,2,3};
__constant__ int c_TBJ[NWARP1] = {0,1,2,3,1,2,3,2,3,3};

// ---------------- PTX helpers ----------------
__device__ __forceinline__ void ffma2(ull &d, ull a, ull b) {
    asm("fma.rn.f32x2 %0, %1, %2, %0;" : "+l"(d) : "l"(a), "l"(b));
}
__device__ __forceinline__ ull dupf(float c) {
    ull r;
    unsigned u = __float_as_uint(c);
    asm("mov.b64 %0, {%1, %1};" : "=l"(r) : "r"(u));
    return r;
}
__device__ __forceinline__ void mbar_init(uint32_t mbar, uint32_t cnt) {
    asm volatile("mbarrier.init.shared.b64 [%0], %1;" :: "r"(mbar), "r"(cnt) : "memory");
}
__device__ __forceinline__ void mbar_expect_tx(uint32_t mbar, uint32_t bytes) {
    asm volatile("mbarrier.arrive.expect_tx.shared.b64 _, [%0], %1;"
                 :: "r"(mbar), "r"(bytes) : "memory");
}
__device__ __forceinline__ void mbar_wait(uint32_t mbar, uint32_t phase) {
    asm volatile(
        "{\n\t.reg .pred P;\n\t"
        "WL_%=:\n\t"
        "mbarrier.try_wait.parity.acquire.cta.shared::cta.b64 P, [%0], %1, 0x989680;\n\t"
        "@!P bra WL_%=;\n\t}"
        :: "r"(mbar), "r"(phase) : "memory");
}
__device__ __forceinline__ void bulk_g2s(uint32_t dst, const void* src,
                                         uint32_t bytes, uint32_t mbar) {
    asm volatile(
        "cp.async.bulk.shared::cluster.global.mbarrier::complete_tx::bytes [%0], [%1], %2, [%3];"
        :: "r"(dst), "l"(src), "r"(bytes), "r"(mbar) : "memory");
}
__device__ __forceinline__ void bulk_s2g(void* dst, uint32_t src, uint32_t bytes) {
    asm volatile(
        "cp.async.bulk.global.shared::cta.bulk_group [%0], [%1], %2;"
        :: "l"(dst), "r"(src), "r"(bytes) : "memory");
}
__device__ __forceinline__ void bulk_commit() {
    asm volatile("cp.async.bulk.commit_group;" ::: "memory");
}
__device__ __forceinline__ void bulk_wait_read0() {
    asm volatile("cp.async.bulk.wait_group.read 0;" ::: "memory");
}
__device__ __forceinline__ void bulk_wait_all0() {
    asm volatile("cp.async.bulk.wait_group 0;" ::: "memory");
}
__device__ __forceinline__ void fence_async() {
    asm volatile("fence.proxy.async.shared::cta;" ::: "memory");
}

__device__ __forceinline__ const float* seg_base(int k,
        const float* __restrict__ W1, const float* __restrict__ b1,
        const float* __restrict__ W2, const float* __restrict__ b2,
        int &stride, int &kl) {
    if (k < SEG_B0) { stride = L0; kl = k;          return W1; }
    if (k < SEG_B1) { stride = L1; kl = k - SEG_B0; return b1; }
    if (k < SEG_B2) { stride = L2; kl = k - SEG_B1; return W2; }
    stride = L3; kl = k - SEG_B2; return b2;
}

// ---------------- pass 1: Gram (R8-exact) ----------------
__global__ __launch_bounds__(320, 1)
void gram_kernel(const float* __restrict__ W1, const float* __restrict__ b1,
                 const float* __restrict__ W2, const float* __restrict__ b2) {
    extern __shared__ char sm[];
    const uint32_t sb = (uint32_t)__cvta_generic_to_shared(sm);
    const uint32_t mb_full = sb;
    const int tid  = threadIdx.x;
    const int w    = tid >> 5;
    const int lane = tid & 31;
    const int bi = c_TBI[w], bj = c_TBJ[w];

    const int per = GNCH / NBLK1, rem = GNCH % NBLK1;
    const int b   = blockIdx.x;
    const int c0  = b * per + (b < rem ? b : rem);
    const int cnt = per + (b < rem ? 1 : 0);

    if (tid == 0) {
#pragma unroll
        for (int s = 0; s < GSTAGES; s++) mbar_init(mb_full + s * 8, 1);
    }
    __syncthreads();

    auto load_chunk = [&](int n) {
        const int chunk = c0 + n;
        const int buf = n % GSTAGES;
        const uint32_t bytes = (chunk == GNCH - 1) ? 1024u : 2048u;
        int stride, kl;
        const float* base = seg_base(chunk * GCH, W1, b1, W2, b2, stride, kl);
        const uint32_t full = mb_full + buf * 8;
        if (lane == 0) mbar_expect_tx(full, bytes * 32);
        __syncwarp();
        bulk_g2s(sb + GOFF + buf * GSTAGE_B + lane * GROW_B,
                 base + (size_t)lane * stride + kl, bytes, full);
    };

    if (w == GPW) {
        for (int n = 0; n < GSTAGES - 1 && n < cnt; n++) load_chunk(n);
    }

    ull acc[64];
#pragma unroll
    for (int p = 0; p < 64; p++) acc[p] = 0ull;

    int stg = 0, ph = 0;
    for (int it = 0; it < cnt; it++) {
        __syncthreads();
        if (w == GPW) {
            int n = it + GSTAGES - 1;
            if (n < cnt) load_chunk(n);
        }
        mbar_wait(mb_full + stg * 8, ph);

        const char* tb = sm + GOFF + stg * GSTAGE_B;
        const int niter = (c0 + it == GNCH - 1) ? 2 : 4;
        for (int g = 0; g < niter; g++) {
            const char* tg = tb + g * 512 + lane * 16;
            ulonglong2 av[8];
#pragma unroll
            for (int r = 0; r < 8; r++)
                av[r] = *reinterpret_cast<const ulonglong2*>(tg + (bi * 8 + r) * GROW_B);
#pragma unroll
            for (int q = 0; q < 8; q++) {
                ulonglong2 bv = *reinterpret_cast<const ulonglong2*>(tg + (bj * 8 + q) * GROW_B);
#pragma unroll
                for (int r = 0; r < 8; r++) {
                    ffma2(acc[r * 8 + q], av[r].x, bv.x);
                    ffma2(acc[r * 8 + q], av[r].y, bv.y);
                }
            }
        }
        if (++stg == GSTAGES) { stg = 0; ph ^= 1; }
    }

#pragma unroll
    for (int p = 0; p < 64; p++) {
        float v = __uint_as_float((unsigned)acc[p]) +
                  __uint_as_float((unsigned)(acc[p] >> 32));
        v += __shfl_xor_sync(0xffffffffu, v, 16);
        v += __shfl_xor_sync(0xffffffffu, v, 8);
        v += __shfl_xor_sync(0xffffffffu, v, 4);
        v += __shfl_xor_sync(0xffffffffu, v, 2);
        v += __shfl_xor_sync(0xffffffffu, v, 1);
        if (lane == 0) g_Gpart[(b * NWARP1 + w) * 64 + p] = v;
    }
}

// ---------------- pass 1b: partials -> K -> coefficient table ----------------
__global__ __launch_bounds__(1024, 1)
void coef_kernel() {
    __shared__ float Gs[32][32];
    __shared__ float Ks[32][33];
    __shared__ float Ssh[32];
    const int tid = threadIdx.x;

    if (tid < NWARP1 * 64) {
        float s0 = 0.f, s1 = 0.f, s2 = 0.f, s3 = 0.f;
#pragma unroll 1
        for (int bb = 0; bb < NBLK1; bb += 4) {
            s0 += g_Gpart[(bb + 0) * (NWARP1 * 64) + tid];
            s1 += g_Gpart[(bb + 1) * (NWARP1 * 64) + tid];
            s2 += g_Gpart[(bb + 2) * (NWARP1 * 64) + tid];
            s3 += g_Gpart[(bb + 3) * (NWARP1 * 64) + tid];
        }
        float s = (s0 + s1) + (s2 + s3);
        int w = tid / 64, pr = tid % 64, r = pr / 8, q = pr % 8;
        Gs[c_TBI[w] * 8 + r][c_TBJ[w] * 8 + q] = s;
    }
    __syncthreads();
    {
        int i = tid >> 5, j = tid & 31;
        if ((i >> 3) > (j >> 3)) Gs[i][j] = Gs[j][i];
    }
    __syncthreads();
    {
        int i = tid >> 5, j = tid & 31;
        float d2 = Gs[i][i] + Gs[j][j] - 2.f * Gs[i][j];
        d2 = fmaxf(d2, 0.f);
        Ks[i][j] = expf(-0.5f * d2);
    }
    __syncthreads();
    if (tid < 32) {
        float s = 0.f;
        for (int j = 1; j < 32; j++) s += Ks[tid][j];
        Ssh[tid] = s;
    }
    __syncthreads();
    {
        int i = tid >> 5, j = tid & 31;
        float v = (j >= 1) ? (EPSV / (float)NPART) * Ks[i][j] : 0.f;
        if (j == i) v += 1.f - 3.f * EPSV * Ssh[i] / (float)NPART;
        g_Cf[j * 32 + i] = v;               // float, [j][i]
    }
}

// ---------------- pass 2: out = C @ theta (spread/multicast mapping) ----------------
// 2 CTAs/SM x 8 warps; warp w owns k-float window [32w, 32w+32) of each row.
// lane = (kq = lane&7, pg = lane>>3): kq picks 16B of the 128B window (4 k),
// pg picks 8 particles. Per j: 1 spread theta LDS.128 + 2 spread coef LDS.128
// (both 4x-multicast, ~1-2 phases each) + 16 FFMA2.
__global__ __launch_bounds__(256, 2)
void apply_kernel(const float* __restrict__ W1, const float* __restrict__ b1,
                  const float* __restrict__ W2, const float* __restrict__ b2,
                  float* __restrict__ out) {
    extern __shared__ char sm[];
    const uint32_t sb = (uint32_t)__cvta_generic_to_shared(sm);
    const uint32_t mb_full = sb;
    char* csb = sm + 64;                 // coef table: float[32 j][32 i] = 4KB
    const int tid  = threadIdx.x;
    const int w    = tid >> 5;
    const int lane = tid & 31;
    const int kq   = lane & 7;
    const int pg   = lane >> 3;          // 0..3

    if (tid == 0) {
#pragma unroll
        for (int s = 0; s < ASTAGES; s++) mbar_init(mb_full + s * 8, 1);
    }
    {   // stage coef table (float)
        float* csf = reinterpret_cast<float*>(csb);
        for (int idx = tid; idx < 1024; idx += 256) csf[idx] = g_Cf[idx];
    }
    __syncthreads();

    const int per = ANCH / NBLK2, rem = ANCH % NBLK2;
    const int b   = blockIdx.x;
    const int s0  = b * per + (b < rem ? b : rem);
    const int cnt = per + (b < rem ? 1 : 0);

    auto load_chunk = [&](int n) {                // producer warp, lane-parallel
        const int buf = n % ASTAGES;
        int stride, kl;
        const float* base = seg_base((s0 + n) * ACH, W1, b1, W2, b2, stride, kl);
        const uint32_t full = mb_full + buf * 8;
        if (lane == 0) mbar_expect_tx(full, 32 * 1024u);
        __syncwarp();
        bulk_g2s(sb + AOFF + buf * ASTAGE_B + lane * AROW_B,
                 base + (size_t)lane * stride + kl, 1024u, full);
    };

    if (w == APW) {
        for (int n = 0; n < ASTAGES - 1 && n < cnt; n++) load_chunk(n);
    }

    int stg = 0, ph = 0;
    for (int it = 0; it < cnt; it++) {
        __syncthreads();   // transposed output of it-1 visible; reads of it-1 done
        if (w == APW) {
            if (it > 0) {  // drain buf (it-1)%3: 1KB contiguous row per lane
                const int dstg = (it - 1) % ASTAGES;
                fence_async();
                bulk_s2g(out + (size_t)lane * P_TOT + (size_t)(s0 + it - 1) * ACH,
                         sb + AOFF + dstg * ASTAGE_B + lane * AROW_B, 1024u);
                bulk_commit();
            }
            int n = it + ASTAGES - 1;
            if (n < cnt) {
                bulk_wait_read0();
                load_chunk(n);
            }
        }
        mbar_wait(mb_full + stg * 8, ph);

        char* tb = sm + AOFF + stg * ASTAGE_B;
        const char* tw = tb + w * 128 + kq * 16;   // this lane's 16B theta slice

        ull acc[16];
#pragma unroll
        for (int p = 0; p < 16; p++) acc[p] = 0ull;

#pragma unroll
        for (int j = 0; j < 32; j++) {
            ulonglong2 tv = *reinterpret_cast<const ulonglong2*>(tw + j * AROW_B);
            const float4* cp = reinterpret_cast<const float4*>(csb + j * 128 + pg * 32);
            float4 ca = cp[0], cb = cp[1];         // coefs for particles pg*8..pg*8+7
            ffma2(acc[0],  dupf(ca.x), tv.x);  ffma2(acc[1],  dupf(ca.x), tv.y);
            ffma2(acc[2],  dupf(ca.y), tv.x);  ffma2(acc[3],  dupf(ca.y), tv.y);
            ffma2(acc[4],  dupf(ca.z), tv.x);  ffma2(acc[5],  dupf(ca.z), tv.y);
            ffma2(acc[6],  dupf(ca.w), tv.x);  ffma2(acc[7],  dupf(ca.w), tv.y);
            ffma2(acc[8],  dupf(cb.x), tv.x);  ffma2(acc[9],  dupf(cb.x), tv.y);
            ffma2(acc[10], dupf(cb.y), tv.x);  ffma2(acc[11], dupf(cb.y), tv.y);
            ffma2(acc[12], dupf(cb.z), tv.x);  ffma2(acc[13], dupf(cb.z), tv.y);
            ffma2(acc[14], dupf(cb.w), tv.x);  ffma2(acc[15], dupf(cb.w), tv.y);
        }

        __syncthreads();                          // all reads of tb done
        {   // transpose: particle p gets acc pair (k-contiguous 16B) at its row
#pragma unroll
            for (int h = 0; h < 8; h++) {
                int p = pg * 8 + h;
                *reinterpret_cast<ulonglong2*>(tb + p * AROW_B + w * 128 + kq * 16) =
                    make_ulonglong2(acc[2 * h], acc[2 * h + 1]);
            }
        }
        if (++stg == ASTAGES) { stg = 0; ph ^= 1; }
    }

    __syncthreads();                              // final transposed buffer visible
    if (w == APW && cnt > 0) {                    // drain last chunk
        const int dstg = (cnt - 1) % ASTAGES;
        fence_async();
        bulk_s2g(out + (size_t)lane * P_TOT + (size_t)(s0 + cnt - 1) * ACH,
                 sb + AOFF + dstg * ASTAGE_B + lane * AROW_B, 1024u);
        bulk_commit();
        bulk_wait_all0();
    }
}

// ---------------- launch ----------------
extern "C" void kernel_launch(void* const* d_in, const int* in_sizes, int n_in,
                              void* d_out, int out_size) {
    const float* W1 = (const float*)d_in[0];
    const float* b1 = (const float*)d_in[1];
    const float* W2 = (const float*)d_in[2];
    const float* b2 = (const float*)d_in[3];
    float* out = (float*)d_out;

    cudaFuncSetAttribute(gram_kernel,  cudaFuncAttributeMaxDynamicSharedMemorySize, GSMEM);
    cudaFuncSetAttribute(apply_kernel, cudaFuncAttributeMaxDynamicSharedMemorySize, ASMEM);

    gram_kernel<<<NBLK1, 320, GSMEM>>>(W1, b1, W2, b2);
    coef_kernel<<<1, 1024>>>();
    apply_kernel<<<NBLK2, 256, ASMEM>>>(W1, b1, W2, b2, out);
}